// round 10
// baseline (speedup 1.0000x reference)
#include <cuda_runtime.h>
#include <math.h>

#define NDIMS 3
#define HN    256
#define FN    16
#define MTOT  65536
#define TCOND 100
#define NJC   8
#define JCW   (HN / NJC)

// ---- NUFFT parameters (unchanged from round 9, rel_err 2.1e-4) ----
#define NGRID 896          // sigma = 896/513 = 1.747
#define WK    5            // window width (odd -> round-to-nearest)
#define NPAD  (NGRID + 5)  // 901 rows; row r <-> grid point l = r-2
#define RSTR  20           // row stride in floats (80B)
#define BETA  11.2113f     // pi*w*(1 - 1/(2*sigma))
#define NSQ   64

#define NBLK  148
#define SPB   443          // samples per x-block (148*443 >= 65536)

__device__ __align__(16) float g_tab[NDIMS][NPAD][RSTR];
__device__ float g_c[NDIMS][FN];
__device__ __align__(16) float g_part[MTOT][NDIMS][FN];   // 12.6MB staging

// ---------------- packed f32x2 helpers ----------------
__device__ __forceinline__ unsigned long long pk2(float lo, float hi) {
    unsigned long long r;
    asm("mov.b64 %0, {%1, %2};" : "=l"(r) : "f"(lo), "f"(hi));
    return r;
}
__device__ __forceinline__ void upk2(unsigned long long v, float& lo, float& hi) {
    asm("mov.b64 {%0, %1}, %2;" : "=f"(lo), "=f"(hi) : "l"(v));
}
__device__ __forceinline__ unsigned long long fma2(unsigned long long a,
                                                   unsigned long long b,
                                                   unsigned long long c) {
    unsigned long long d;
    asm("fma.rn.f32x2 %0, %1, %2, %3;" : "=l"(d) : "l"(a), "l"(b), "l"(c));
    return d;
}
__device__ __forceinline__ unsigned long long mul2(unsigned long long a,
                                                   unsigned long long b) {
    unsigned long long d;
    asm("mul.rn.f32x2 %0, %1, %2;" : "=l"(d) : "l"(a), "l"(b));
    return d;
}
__device__ __forceinline__ float es_w(float z) {
    float s2 = fmaxf(1.0f - z * z, 0.0f);
    return __expf(BETA * (sqrtf(s2) - 1.0f));
}

// ---------------- kernel 1: fused psihat + fine-grid table build ----------------
// (identical to round 9, which passed)
#define PREP_SQ    0
#define PREP_PHI   257
#define PREP_A     328
#define PREP_B     (PREP_A + HN * FN)
#define PREP_PART  (PREP_B + HN * FN)
#define PREP_FLOATS (PREP_PART + 32 * NJC * FN)

__global__ void __launch_bounds__(256, 4)
prep_kernel(const float* __restrict__ fr, const float* __restrict__ fi) {
    extern __shared__ float sm[];
    float* sq   = sm + PREP_SQ;
    float* sphi = sm + PREP_PHI;
    float* sA   = sm + PREP_A;
    float* sB   = sm + PREP_B;
    float* part = sm + PREP_PART;

    const int n = blockIdx.y;
    const int tid = threadIdx.x;

    if (tid <= NSQ) {
        float z = -1.0f + (float)tid * (2.0f / NSQ);
        float phi = __expf(BETA * (sqrtf(fmaxf(1.0f - z * z, 0.0f)) - 1.0f));
        float cI = (tid == 0 || tid == NSQ) ? 1.0f : ((tid & 1) ? 4.0f : 2.0f);
        sphi[tid] = cI * phi * ((2.0f / NSQ) / 3.0f);
    }
    __syncthreads();

    {
        int k = tid + 1;
        float freq = (float)k * ((float)WK / (float)NGRID);
        float I = 0.0f;
#pragma unroll 4
        for (int i = 0; i <= NSQ; i++) {
            float z = -1.0f + (float)i * (2.0f / NSQ);
            I += sphi[i] * cospif(freq * z);
        }
        sq[k] = 2.0f / ((float)WK * I);
        if (tid == 0) {
            float I0 = 0.0f;
            for (int i = 0; i <= NSQ; i++) I0 += sphi[i];
            sq[0] = 2.0f / ((float)WK * I0);
        }
    }
    __syncthreads();

    for (int idx = tid; idx < HN * FN; idx += 256) {
        int f = idx & (FN - 1);
        int jm1 = idx >> 4;
        float q = sq[jm1 + 1];
        int src = (n * HN + (HN - 1 - jm1)) * FN + f;
        sA[idx] =  2.0f * q * fr[src];
        sB[idx] = -2.0f * q * fi[src];
    }
    __syncthreads();

    const int rl = tid & 31;
    const int jc = tid >> 5;
    const int r  = blockIdx.x * 32 + rl;
    {
        float xr = (float)(r - 2) * (1.0f / (float)NGRID);
        int jstart = jc * JCW + 1;
        float c0, s0, c1, s1;
        sincospif(2.0f * (float)jstart * xr, &s0, &c0);
        sincospif(2.0f * xr, &s1, &c1);
        unsigned long long cc = pk2(c0, c0), ss = pk2(s0, s0);
        unsigned long long C1 = pk2(c1, c1), S1 = pk2(s1, s1), nS1 = pk2(-s1, -s1);

        const ulonglong2* An = (const ulonglong2*)sA;
        const ulonglong2* Bn = (const ulonglong2*)sB;

        unsigned long long acc[8];
#pragma unroll
        for (int p = 0; p < 8; p++) acc[p] = 0ull;

        for (int jj = 0; jj < JCW; jj++) {
            int j0 = jc * JCW + jj;
            ulonglong2 a0 = An[4 * j0 + 0];
            ulonglong2 a1 = An[4 * j0 + 1];
            ulonglong2 a2 = An[4 * j0 + 2];
            ulonglong2 a3 = An[4 * j0 + 3];
            ulonglong2 b0 = Bn[4 * j0 + 0];
            ulonglong2 b1 = Bn[4 * j0 + 1];
            ulonglong2 b2 = Bn[4 * j0 + 2];
            ulonglong2 b3 = Bn[4 * j0 + 3];

            acc[0] = fma2(cc, a0.x, acc[0]);
            acc[1] = fma2(cc, a0.y, acc[1]);
            acc[2] = fma2(cc, a1.x, acc[2]);
            acc[3] = fma2(cc, a1.y, acc[3]);
            acc[4] = fma2(cc, a2.x, acc[4]);
            acc[5] = fma2(cc, a2.y, acc[5]);
            acc[6] = fma2(cc, a3.x, acc[6]);
            acc[7] = fma2(cc, a3.y, acc[7]);
            acc[0] = fma2(ss, b0.x, acc[0]);
            acc[1] = fma2(ss, b0.y, acc[1]);
            acc[2] = fma2(ss, b1.x, acc[2]);
            acc[3] = fma2(ss, b1.y, acc[3]);
            acc[4] = fma2(ss, b2.x, acc[4]);
            acc[5] = fma2(ss, b2.y, acc[5]);
            acc[6] = fma2(ss, b3.x, acc[6]);
            acc[7] = fma2(ss, b3.y, acc[7]);

            unsigned long long t0 = mul2(cc, C1);
            unsigned long long t1 = mul2(cc, S1);
            cc = fma2(ss, nS1, t0);
            ss = fma2(ss, C1,  t1);
        }

        float* pp = &part[(rl * NJC + jc) * FN];
#pragma unroll
        for (int p = 0; p < 8; p++) {
            float lo, hi;
            upk2(acc[p], lo, hi);
            pp[2 * p + 0] = lo;
            pp[2 * p + 1] = hi;
        }
    }
    __syncthreads();

    const float q0 = sq[0];
    for (int idx = tid; idx < 32 * FN; idx += 256) {
        int rl2 = idx >> 4;
        int f   = idx & (FN - 1);
        int rr  = blockIdx.x * 32 + rl2;
        if (rr < NPAD) {
            float v = q0;
#pragma unroll
            for (int q = 0; q < NJC; q++)
                v += part[(rl2 * NJC + q) * FN + f];
            g_tab[n][rr][f] = v;
        }
    }
}

// ---------------- kernel 2 (E1): per-dim spread ----------------
// grid = (148, 3), block = 384, 3 blocks/SM. smem = dim table 72KB + red 256B.
#define DT_FLOATS (NPAD * RSTR)          // 18020
#define E1_RED    DT_FLOATS
#define E1_FLOATS (DT_FLOATS + 64)
#define E1_SMEM_BYTES (E1_FLOATS * 4)

__global__ void __launch_bounds__(384, 3)
spread_kernel(const float* __restrict__ x) {
    extern __shared__ float sm[];
    float* dtab = sm;
    float* red  = sm + E1_RED;           // [4][16]

    const int n   = blockIdx.y;
    const int tid = threadIdx.x;

    // copy this dim's table L2 -> smem
    {
        const float4* src = (const float4*)&g_tab[n][0][0];
        float4* dst = (float4*)dtab;
        for (int idx = tid; idx < DT_FLOATS / 4; idx += 384)
            dst[idx] = src[idx];
    }
    __syncthreads();

    // conditional c_n: only x-block 0, warps 0..3
    if (blockIdx.x == 0 && tid < 128) {
        float val[FN];
#pragma unroll
        for (int f = 0; f < FN; f++) val[f] = 0.0f;
        if (tid < TCOND) {
            float t = 0.01f + 0.01f * (float)tid;
            float xg = t * (float)NGRID;
            float rc = floorf(xg + 0.5f);
            float dlt = xg - rc;
            int r0 = (int)rc;
            const float* rowp = dtab + r0 * RSTR;
            float acc[FN];
#pragma unroll
            for (int f = 0; f < FN; f++) acc[f] = 0.0f;
#pragma unroll
            for (int tt = 0; tt < WK; tt++) {
                float wgt = es_w((dlt + (float)(2 - tt)) * 0.4f);
                const float4* p4 = (const float4*)(rowp + tt * RSTR);
#pragma unroll
                for (int cq = 0; cq < 4; cq++) {
                    float4 v = p4[cq];
                    acc[4 * cq + 0] = fmaf(wgt, v.x, acc[4 * cq + 0]);
                    acc[4 * cq + 1] = fmaf(wgt, v.y, acc[4 * cq + 1]);
                    acc[4 * cq + 2] = fmaf(wgt, v.z, acc[4 * cq + 2]);
                    acc[4 * cq + 3] = fmaf(wgt, v.w, acc[4 * cq + 3]);
                }
            }
            float wt = (tid == 0 || tid == TCOND - 1) ? 0.005f : 0.01f;
#pragma unroll
            for (int f = 0; f < FN; f++) val[f] = wt * fmaxf(acc[f], 0.0f);
        }
#pragma unroll
        for (int off = 16; off; off >>= 1)
#pragma unroll
            for (int f = 0; f < FN; f++)
                val[f] += __shfl_down_sync(0xffffffffu, val[f], off);
        if ((tid & 31) == 0) {
            int w = tid >> 5;
#pragma unroll
            for (int f = 0; f < FN; f++)
                red[w * FN + f] = val[f];
        }
    }

    // main spread: pairs (192), 3 sample slots each
    const int pr = tid >> 1;
    const int h  = tid & 1;
    const int base = blockIdx.x * SPB;

#pragma unroll
    for (int s = 0; s < 3; s++) {
        int slot = s * 192 + pr;
        int m = base + slot;
        if (slot < SPB && m < MTOT) {
            float xn = x[3 * m + n];
            float xg = xn * (float)NGRID;
            float rc = floorf(xg + 0.5f);
            float dlt = xg - rc;
            int r0 = (int)rc;

            float w0 = es_w((dlt + 2.0f) * 0.4f);
            float w1 = es_w((dlt + 1.0f) * 0.4f);
            float w2 = es_w( dlt         * 0.4f);
            float w3 = es_w((dlt - 1.0f) * 0.4f);
            float w4 = es_w((dlt - 2.0f) * 0.4f);

            const float* rowp = dtab + r0 * RSTR + h * 8;
            unsigned long long acc[4];
#pragma unroll
            for (int q = 0; q < 4; q++) acc[q] = 0ull;

            float wts[WK] = {w0, w1, w2, w3, w4};
#pragma unroll
            for (int t = 0; t < WK; t++) {
                unsigned long long wb = pk2(wts[t], wts[t]);
                const ulonglong2* p2 = (const ulonglong2*)(rowp + t * RSTR);
                ulonglong2 va = p2[0];
                ulonglong2 vb = p2[1];
                acc[0] = fma2(wb, va.x, acc[0]);
                acc[1] = fma2(wb, va.y, acc[1]);
                acc[2] = fma2(wb, vb.x, acc[2]);
                acc[3] = fma2(wb, vb.y, acc[3]);
            }

            float4 o0, o1;
            {
                float l0, h0, l1, h1;
                upk2(acc[0], l0, h0); upk2(acc[1], l1, h1);
                o0 = make_float4(fmaxf(l0, 0.0f), fmaxf(h0, 0.0f),
                                 fmaxf(l1, 0.0f), fmaxf(h1, 0.0f));
                upk2(acc[2], l0, h0); upk2(acc[3], l1, h1);
                o1 = make_float4(fmaxf(l0, 0.0f), fmaxf(h0, 0.0f),
                                 fmaxf(l1, 0.0f), fmaxf(h1, 0.0f));
            }
            float4* dst = (float4*)&g_part[m][n][h * 8];
            dst[0] = o0;
            dst[1] = o1;
        }
    }

    // finish conditional
    if (blockIdx.x == 0) {
        __syncthreads();
        if (tid < FN) {
            float s = red[tid] + red[FN + tid] + red[2 * FN + tid] + red[3 * FN + tid];
            g_c[n][tid] = 1.0f / s;
        }
    }
}

// ---------------- kernel 3 (E2): combine ----------------
__global__ void __launch_bounds__(512)
combine_kernel(const float* __restrict__ lam, float* __restrict__ out) {
    __shared__ float sLam2[FN];
    if (threadIdx.x < FN)
        sLam2[threadIdx.x] = lam[threadIdx.x] * g_c[0][threadIdx.x]
                           * g_c[1][threadIdx.x] * g_c[2][threadIdx.x];
    __syncthreads();

    const int m = blockIdx.x * 512 + threadIdx.x;

    float prod[FN];
#pragma unroll
    for (int n = 0; n < NDIMS; n++) {
        const float4* p = (const float4*)&g_part[m][n][0];
        float4 v0 = p[0], v1 = p[1], v2 = p[2], v3 = p[3];
        float v[FN] = {v0.x, v0.y, v0.z, v0.w, v1.x, v1.y, v1.z, v1.w,
                       v2.x, v2.y, v2.z, v2.w, v3.x, v3.y, v3.z, v3.w};
#pragma unroll
        for (int f = 0; f < FN; f++)
            prod[f] = (n == 0) ? v[f] : prod[f] * v[f];
    }

    float s = 0.0f;
#pragma unroll
    for (int f = 0; f < FN; f++)
        s = fmaf(prod[f], sLam2[f], s);
    out[m] = s;
}

// ---------------- launch ----------------
extern "C" void kernel_launch(void* const* d_in, const int* in_sizes, int n_in,
                              void* d_out, int out_size) {
    const float* x   = (const float*)d_in[0];
    const float* fr  = (const float*)d_in[1];
    const float* fi  = (const float*)d_in[2];
    const float* lam = (const float*)d_in[3];
    float* out = (float*)d_out;

    const int prep_smem = PREP_FLOATS * (int)sizeof(float);
    cudaFuncSetAttribute(prep_kernel,
                         cudaFuncAttributeMaxDynamicSharedMemorySize, prep_smem);
    prep_kernel<<<dim3((NPAD + 31) / 32, NDIMS), 256, prep_smem>>>(fr, fi);

    cudaFuncSetAttribute(spread_kernel,
                         cudaFuncAttributeMaxDynamicSharedMemorySize, E1_SMEM_BYTES);
    spread_kernel<<<dim3(NBLK, NDIMS), 384, E1_SMEM_BYTES>>>(x);

    combine_kernel<<<MTOT / 512, 512>>>(lam, out);
}

// round 11
// speedup vs baseline: 1.0667x; 1.0667x over previous
#include <cuda_runtime.h>
#include <math.h>

#define NDIMS 3
#define HN    256
#define FN    16
#define MTOT  65536
#define TCOND 100
#define NJC   16           // j-chunks per row (prep)
#define JCW   (HN / NJC)   // 16 j per chunk
#define RPB   16           // rows per prep block

// ---- NUFFT parameters (validated round 9: rel_err 2.14e-4) ----
#define NGRID 896          // sigma = 896/513 = 1.747
#define WK    5            // window width (odd -> round-to-nearest)
#define NPAD  (NGRID + 5)  // 901 rows; row r <-> grid point l = r-2
#define RSTR  20           // row stride in floats (80B)
#define BETA  11.2113f     // pi*w*(1 - 1/(2*sigma))
#define NSQ   64

#define NBLK  148
#define SPB   443          // samples per eval block (148*443 >= 65536)

__device__ __align__(16) float g_tab[NDIMS][NPAD][RSTR];

// ---------------- packed f32x2 helpers ----------------
__device__ __forceinline__ unsigned long long pk2(float lo, float hi) {
    unsigned long long r;
    asm("mov.b64 %0, {%1, %2};" : "=l"(r) : "f"(lo), "f"(hi));
    return r;
}
__device__ __forceinline__ void upk2(unsigned long long v, float& lo, float& hi) {
    asm("mov.b64 {%0, %1}, %2;" : "=f"(lo), "=f"(hi) : "l"(v));
}
__device__ __forceinline__ unsigned long long fma2(unsigned long long a,
                                                   unsigned long long b,
                                                   unsigned long long c) {
    unsigned long long d;
    asm("fma.rn.f32x2 %0, %1, %2, %3;" : "=l"(d) : "l"(a), "l"(b), "l"(c));
    return d;
}
__device__ __forceinline__ unsigned long long mul2(unsigned long long a,
                                                   unsigned long long b) {
    unsigned long long d;
    asm("mul.rn.f32x2 %0, %1, %2;" : "=l"(d) : "l"(a), "l"(b));
    return d;
}
__device__ __forceinline__ float es_w(float z) {
    float s2 = fmaxf(1.0f - z * z, 0.0f);
    return __expf(BETA * (sqrtf(s2) - 1.0f));
}

// ---------------- kernel 1: fused psihat + fine-grid table build ----------------
// grid = (57, 3), block = 256 = 16 rows x 16 j-chunks.
// smem: sq[257] @0 | sphi[65] @257 | sA @328 (16B aligned) | sB | part[16*16*16]
#define PREP_SQ    0
#define PREP_PHI   257
#define PREP_A     328
#define PREP_B     (PREP_A + HN * FN)
#define PREP_PART  (PREP_B + HN * FN)
#define PREP_FLOATS (PREP_PART + RPB * NJC * FN)

__global__ void __launch_bounds__(256, 4)
prep_kernel(const float* __restrict__ fr, const float* __restrict__ fi) {
    extern __shared__ float sm[];
    float* sq   = sm + PREP_SQ;
    float* sphi = sm + PREP_PHI;
    float* sA   = sm + PREP_A;
    float* sB   = sm + PREP_B;
    float* part = sm + PREP_PART;

    const int n = blockIdx.y;
    const int tid = threadIdx.x;

    if (tid <= NSQ) {
        float z = -1.0f + (float)tid * (2.0f / NSQ);
        float phi = __expf(BETA * (sqrtf(fmaxf(1.0f - z * z, 0.0f)) - 1.0f));
        float cI = (tid == 0 || tid == NSQ) ? 1.0f : ((tid & 1) ? 4.0f : 2.0f);
        sphi[tid] = cI * phi * ((2.0f / NSQ) / 3.0f);
    }
    __syncthreads();

    {
        int k = tid + 1;
        float freq = (float)k * ((float)WK / (float)NGRID);
        float I = 0.0f;
#pragma unroll 4
        for (int i = 0; i <= NSQ; i++) {
            float z = -1.0f + (float)i * (2.0f / NSQ);
            I += sphi[i] * cospif(freq * z);
        }
        sq[k] = 2.0f / ((float)WK * I);
        if (tid == 0) {
            float I0 = 0.0f;
            for (int i = 0; i <= NSQ; i++) I0 += sphi[i];
            sq[0] = 2.0f / ((float)WK * I0);
        }
    }
    __syncthreads();

    for (int idx = tid; idx < HN * FN; idx += 256) {
        int f = idx & (FN - 1);
        int jm1 = idx >> 4;
        float q = sq[jm1 + 1];
        int src = (n * HN + (HN - 1 - jm1)) * FN + f;
        sA[idx] =  2.0f * q * fr[src];
        sB[idx] = -2.0f * q * fi[src];
    }
    __syncthreads();

    // series at 16 rows x 16 j-chunks (16 j each)
    const int rl = tid & (RPB - 1);
    const int jc = tid >> 4;
    const int r  = blockIdx.x * RPB + rl;
    {
        float xr = (float)(r - 2) * (1.0f / (float)NGRID);
        int jstart = jc * JCW + 1;
        float c0, s0, c1, s1;
        sincospif(2.0f * (float)jstart * xr, &s0, &c0);
        sincospif(2.0f * xr, &s1, &c1);
        unsigned long long cc = pk2(c0, c0), ss = pk2(s0, s0);
        unsigned long long C1 = pk2(c1, c1), S1 = pk2(s1, s1), nS1 = pk2(-s1, -s1);

        const ulonglong2* An = (const ulonglong2*)sA;
        const ulonglong2* Bn = (const ulonglong2*)sB;

        unsigned long long acc[8];
#pragma unroll
        for (int p = 0; p < 8; p++) acc[p] = 0ull;

#pragma unroll 2
        for (int jj = 0; jj < JCW; jj++) {
            int j0 = jc * JCW + jj;
            ulonglong2 a0 = An[4 * j0 + 0];
            ulonglong2 a1 = An[4 * j0 + 1];
            ulonglong2 a2 = An[4 * j0 + 2];
            ulonglong2 a3 = An[4 * j0 + 3];
            ulonglong2 b0 = Bn[4 * j0 + 0];
            ulonglong2 b1 = Bn[4 * j0 + 1];
            ulonglong2 b2 = Bn[4 * j0 + 2];
            ulonglong2 b3 = Bn[4 * j0 + 3];

            acc[0] = fma2(cc, a0.x, acc[0]);
            acc[1] = fma2(cc, a0.y, acc[1]);
            acc[2] = fma2(cc, a1.x, acc[2]);
            acc[3] = fma2(cc, a1.y, acc[3]);
            acc[4] = fma2(cc, a2.x, acc[4]);
            acc[5] = fma2(cc, a2.y, acc[5]);
            acc[6] = fma2(cc, a3.x, acc[6]);
            acc[7] = fma2(cc, a3.y, acc[7]);
            acc[0] = fma2(ss, b0.x, acc[0]);
            acc[1] = fma2(ss, b0.y, acc[1]);
            acc[2] = fma2(ss, b1.x, acc[2]);
            acc[3] = fma2(ss, b1.y, acc[3]);
            acc[4] = fma2(ss, b2.x, acc[4]);
            acc[5] = fma2(ss, b2.y, acc[5]);
            acc[6] = fma2(ss, b3.x, acc[6]);
            acc[7] = fma2(ss, b3.y, acc[7]);

            unsigned long long t0 = mul2(cc, C1);
            unsigned long long t1 = mul2(cc, S1);
            cc = fma2(ss, nS1, t0);
            ss = fma2(ss, C1,  t1);
        }

        float* pp = &part[(rl * NJC + jc) * FN];
#pragma unroll
        for (int p = 0; p < 8; p++) {
            float lo, hi;
            upk2(acc[p], lo, hi);
            pp[2 * p + 0] = lo;
            pp[2 * p + 1] = hi;
        }
    }
    __syncthreads();

    // reduce: 256 threads = 16 rows x 16 f, sum 16 chunks each
    {
        const float q0 = sq[0];
        int rl2 = tid >> 4;
        int f   = tid & (FN - 1);
        int rr  = blockIdx.x * RPB + rl2;
        if (rr < NPAD) {
            float v = q0;
#pragma unroll
            for (int q = 0; q < NJC; q++)
                v += part[(rl2 * NJC + q) * FN + f];
            g_tab[n][rr][f] = v;
        }
    }
}

// ---------------- kernel 2: fused lamprep + eval ----------------
// grid = 148, block = 512, 1 thread per sample (443 active).
#define TAB_FLOATS (NDIMS * NPAD * RSTR)     // 54060 floats = 216.2KB
#define EV_WSUM   TAB_FLOATS                 // [12][16]
#define EV_SC     (EV_WSUM + 12 * FN)
#define EV_LAM2   (EV_SC + NDIMS * FN)
#define EV_FLOATS (EV_LAM2 + FN)
#define EV_SMEM_BYTES (EV_FLOATS * 4)

__global__ void __launch_bounds__(512, 1)
eval_kernel(const float* __restrict__ x,
            const float* __restrict__ lam,
            float* __restrict__ out) {
    extern __shared__ float sm[];
    float* tab   = sm;
    float* wsum  = sm + EV_WSUM;
    float* sc    = sm + EV_SC;
    float* sLam2 = sm + EV_LAM2;

    const int tid = threadIdx.x;

    // table broadcast L2 -> smem
    {
        const float4* src = (const float4*)&g_tab[0][0][0];
        float4* dst = (float4*)tab;
        for (int idx = tid; idx < TAB_FLOATS / 4; idx += 512)
            dst[idx] = src[idx];
    }
    __syncthreads();

    // --- lamprep stage 1: warps 0..11 (n = tid>>7, i = tid&127) ---
    if (tid < NDIMS * 128) {
        int n = tid >> 7;
        int i = tid & 127;
        float val[FN];
#pragma unroll
        for (int f = 0; f < FN; f++) val[f] = 0.0f;
        if (i < TCOND) {
            float t = 0.01f + 0.01f * (float)i;
            float xg = t * (float)NGRID;
            float rc = floorf(xg + 0.5f);
            float dlt = xg - rc;
            int r0 = (int)rc;
            const float* rowp = tab + n * (NPAD * RSTR) + r0 * RSTR;
            float acc[FN];
#pragma unroll
            for (int f = 0; f < FN; f++) acc[f] = 0.0f;
#pragma unroll
            for (int tt = 0; tt < WK; tt++) {
                float wgt = es_w((dlt + (float)(2 - tt)) * 0.4f);
                const float4* p4 = (const float4*)(rowp + tt * RSTR);
#pragma unroll
                for (int cq = 0; cq < 4; cq++) {
                    float4 v = p4[cq];
                    acc[4 * cq + 0] = fmaf(wgt, v.x, acc[4 * cq + 0]);
                    acc[4 * cq + 1] = fmaf(wgt, v.y, acc[4 * cq + 1]);
                    acc[4 * cq + 2] = fmaf(wgt, v.z, acc[4 * cq + 2]);
                    acc[4 * cq + 3] = fmaf(wgt, v.w, acc[4 * cq + 3]);
                }
            }
            float wt = (i == 0 || i == TCOND - 1) ? 0.005f : 0.01f;
#pragma unroll
            for (int f = 0; f < FN; f++) val[f] = wt * fmaxf(acc[f], 0.0f);
        }
#pragma unroll
        for (int off = 16; off; off >>= 1)
#pragma unroll
            for (int f = 0; f < FN; f++)
                val[f] += __shfl_down_sync(0xffffffffu, val[f], off);
        if ((tid & 31) == 0) {
            int w = tid >> 5;
#pragma unroll
            for (int f = 0; f < FN; f++)
                wsum[w * FN + f] = val[f];
        }
    }

    // --- main eval: 1 thread per sample, weights hoisted ---
    const int base = blockIdx.x * SPB;
    const bool active = (tid < SPB) && (base + tid < MTOT);
    const int m = base + (active ? tid : 0);

    const float xv0 = x[3 * m + 0];
    const float xv1 = x[3 * m + 1];
    const float xv2 = x[3 * m + 2];

    int rbase[NDIMS];
    unsigned long long wb[NDIMS][WK];
#pragma unroll
    for (int n = 0; n < NDIMS; n++) {
        const float xn = (n == 0) ? xv0 : (n == 1) ? xv1 : xv2;
        float xg = xn * (float)NGRID;
        float rc = floorf(xg + 0.5f);
        float dlt = xg - rc;
        rbase[n] = (int)rc;
#pragma unroll
        for (int t = 0; t < WK; t++) {
            float wgt = es_w((dlt + (float)(2 - t)) * 0.4f);
            wb[n][t] = pk2(wgt, wgt);
        }
    }

    unsigned long long prod[8];
#pragma unroll
    for (int n = 0; n < NDIMS; n++) {
        const float* rowp = tab + n * (NPAD * RSTR) + rbase[n] * RSTR;

        unsigned long long acc[8];
#pragma unroll
        for (int p = 0; p < 8; p++) acc[p] = 0ull;

#pragma unroll
        for (int t = 0; t < WK; t++) {
            unsigned long long w = wb[n][t];
            const ulonglong2* p4 = (const ulonglong2*)(rowp + t * RSTR);
            ulonglong2 v0 = p4[0];
            ulonglong2 v1 = p4[1];
            ulonglong2 v2 = p4[2];
            ulonglong2 v3 = p4[3];
            acc[0] = fma2(w, v0.x, acc[0]);
            acc[1] = fma2(w, v0.y, acc[1]);
            acc[2] = fma2(w, v1.x, acc[2]);
            acc[3] = fma2(w, v1.y, acc[3]);
            acc[4] = fma2(w, v2.x, acc[4]);
            acc[5] = fma2(w, v2.y, acc[5]);
            acc[6] = fma2(w, v3.x, acc[6]);
            acc[7] = fma2(w, v3.y, acc[7]);
        }

#pragma unroll
        for (int p = 0; p < 8; p++) {
            float lo, hi;
            upk2(acc[p], lo, hi);
            unsigned long long r = pk2(fmaxf(lo, 0.0f), fmaxf(hi, 0.0f));
            prod[p] = (n == 0) ? r : mul2(prod[p], r);
        }
    }

    __syncthreads();   // wsum complete

    // --- lamprep stage 2 ---
    if (tid < NDIMS * FN) {
        int nn = tid >> 4;
        int f  = tid & 15;
        float s = wsum[(nn * 4 + 0) * FN + f] + wsum[(nn * 4 + 1) * FN + f]
                + wsum[(nn * 4 + 2) * FN + f] + wsum[(nn * 4 + 3) * FN + f];
        sc[tid] = 1.0f / s;
    }
    __syncthreads();
    if (tid < FN)
        sLam2[tid] = lam[tid] * sc[tid] * sc[FN + tid] * sc[2 * FN + tid];
    __syncthreads();

    // --- dot with lam', write ---
    float s = 0.0f;
#pragma unroll
    for (int p = 0; p < 8; p++) {
        float lo, hi;
        upk2(prod[p], lo, hi);
        s = fmaf(lo, sLam2[2 * p + 0], s);
        s = fmaf(hi, sLam2[2 * p + 1], s);
    }
    if (active) out[m] = s;
}

// ---------------- launch ----------------
extern "C" void kernel_launch(void* const* d_in, const int* in_sizes, int n_in,
                              void* d_out, int out_size) {
    const float* x   = (const float*)d_in[0];
    const float* fr  = (const float*)d_in[1];
    const float* fi  = (const float*)d_in[2];
    const float* lam = (const float*)d_in[3];
    float* out = (float*)d_out;

    const int prep_smem = PREP_FLOATS * (int)sizeof(float);
    cudaFuncSetAttribute(prep_kernel,
                         cudaFuncAttributeMaxDynamicSharedMemorySize, prep_smem);
    prep_kernel<<<dim3((NPAD + RPB - 1) / RPB, NDIMS), 256, prep_smem>>>(fr, fi);

    cudaFuncSetAttribute(eval_kernel,
                         cudaFuncAttributeMaxDynamicSharedMemorySize, EV_SMEM_BYTES);
    eval_kernel<<<NBLK, 512, EV_SMEM_BYTES>>>(x, lam, out);
}

// round 12
// speedup vs baseline: 1.1648x; 1.0920x over previous
#include <cuda_runtime.h>
#include <math.h>

#define NDIMS 3
#define HN    256
#define FN    16
#define MTOT  65536
#define TCOND 100
#define NJC   8            // j-chunks (proven R8/R9 shape)
#define JCW   (HN / NJC)   // 32

// ---- NUFFT parameters (validated: rel_err 2.13e-4) ----
#define NGRID 896          // sigma = 1.747
#define WK    5
#define NPAD  (NGRID + 5)  // 901 rows
#define RSTR  20           // 80B row stride
#define BETA  11.2113f
#define NSQ   64

#define NBLK  148
#define SPB   443

__device__ __align__(16) float g_tab[NDIMS][NPAD][RSTR];

// ---------------- packed f32x2 helpers ----------------
__device__ __forceinline__ unsigned long long pk2(float lo, float hi) {
    unsigned long long r;
    asm("mov.b64 %0, {%1, %2};" : "=l"(r) : "f"(lo), "f"(hi));
    return r;
}
__device__ __forceinline__ void upk2(unsigned long long v, float& lo, float& hi) {
    asm("mov.b64 {%0, %1}, %2;" : "=f"(lo), "=f"(hi) : "l"(v));
}
__device__ __forceinline__ unsigned long long fma2(unsigned long long a,
                                                   unsigned long long b,
                                                   unsigned long long c) {
    unsigned long long d;
    asm("fma.rn.f32x2 %0, %1, %2, %3;" : "=l"(d) : "l"(a), "l"(b), "l"(c));
    return d;
}
__device__ __forceinline__ unsigned long long mul2(unsigned long long a,
                                                   unsigned long long b) {
    unsigned long long d;
    asm("mul.rn.f32x2 %0, %1, %2;" : "=l"(d) : "l"(a), "l"(b));
    return d;
}
__device__ __forceinline__ float es_w(float z) {
    float s2 = fmaxf(1.0f - z * z, 0.0f);
    return __expf(BETA * (sqrtf(s2) - 1.0f));
}

// ---------------- kernel 1: fused psihat + fine-grid table build ----------------
// grid = (29, 3), block = 256 = 32 rows x 8 j-chunks (proven R9 shape).
#define PREP_SQ    0
#define PREP_PHI   257
#define PREP_A     328                       // 16B-aligned
#define PREP_B     (PREP_A + HN * FN)
#define PREP_PART  (PREP_B + HN * FN)
#define PREP_FLOATS (PREP_PART + 32 * NJC * FN)

__global__ void __launch_bounds__(256, 4)
prep_kernel(const float* __restrict__ fr, const float* __restrict__ fi) {
    extern __shared__ float sm[];
    float* sq   = sm + PREP_SQ;
    float* sphi = sm + PREP_PHI;
    float* sA   = sm + PREP_A;
    float* sB   = sm + PREP_B;
    float* part = sm + PREP_PART;

    const int n = blockIdx.y;
    const int tid = threadIdx.x;

    if (tid <= NSQ) {
        float z = -1.0f + (float)tid * (2.0f / NSQ);
        float phi = __expf(BETA * (sqrtf(fmaxf(1.0f - z * z, 0.0f)) - 1.0f));
        float cI = (tid == 0 || tid == NSQ) ? 1.0f : ((tid & 1) ? 4.0f : 2.0f);
        sphi[tid] = cI * phi * ((2.0f / NSQ) / 3.0f);
    }
    __syncthreads();

    {
        int k = tid + 1;
        float freq = (float)k * ((float)WK / (float)NGRID);
        float I = 0.0f;
#pragma unroll 4
        for (int i = 0; i <= NSQ; i++) {
            float z = -1.0f + (float)i * (2.0f / NSQ);
            I += sphi[i] * cospif(freq * z);
        }
        sq[k] = 2.0f / ((float)WK * I);
        if (tid == 0) {
            float I0 = 0.0f;
            for (int i = 0; i <= NSQ; i++) I0 += sphi[i];
            sq[0] = 2.0f / ((float)WK * I0);
        }
    }
    __syncthreads();

    for (int idx = tid; idx < HN * FN; idx += 256) {
        int f = idx & (FN - 1);
        int jm1 = idx >> 4;
        float q = sq[jm1 + 1];
        int src = (n * HN + (HN - 1 - jm1)) * FN + f;
        sA[idx] =  2.0f * q * fr[src];
        sB[idx] = -2.0f * q * fi[src];
    }
    __syncthreads();

    const int rl = tid & 31;
    const int jc = tid >> 5;
    const int r  = blockIdx.x * 32 + rl;
    {
        float xr = (float)(r - 2) * (1.0f / (float)NGRID);
        int jstart = jc * JCW + 1;
        float c0, s0, c1, s1;
        sincospif(2.0f * (float)jstart * xr, &s0, &c0);
        sincospif(2.0f * xr, &s1, &c1);
        unsigned long long cc = pk2(c0, c0), ss = pk2(s0, s0);
        unsigned long long C1 = pk2(c1, c1), S1 = pk2(s1, s1), nS1 = pk2(-s1, -s1);

        const ulonglong2* An = (const ulonglong2*)sA;
        const ulonglong2* Bn = (const ulonglong2*)sB;

        unsigned long long acc[8];
#pragma unroll
        for (int p = 0; p < 8; p++) acc[p] = 0ull;

        for (int jj = 0; jj < JCW; jj++) {
            int j0 = jc * JCW + jj;
            ulonglong2 a0 = An[4 * j0 + 0];
            ulonglong2 a1 = An[4 * j0 + 1];
            ulonglong2 a2 = An[4 * j0 + 2];
            ulonglong2 a3 = An[4 * j0 + 3];
            ulonglong2 b0 = Bn[4 * j0 + 0];
            ulonglong2 b1 = Bn[4 * j0 + 1];
            ulonglong2 b2 = Bn[4 * j0 + 2];
            ulonglong2 b3 = Bn[4 * j0 + 3];

            acc[0] = fma2(cc, a0.x, acc[0]);
            acc[1] = fma2(cc, a0.y, acc[1]);
            acc[2] = fma2(cc, a1.x, acc[2]);
            acc[3] = fma2(cc, a1.y, acc[3]);
            acc[4] = fma2(cc, a2.x, acc[4]);
            acc[5] = fma2(cc, a2.y, acc[5]);
            acc[6] = fma2(cc, a3.x, acc[6]);
            acc[7] = fma2(cc, a3.y, acc[7]);
            acc[0] = fma2(ss, b0.x, acc[0]);
            acc[1] = fma2(ss, b0.y, acc[1]);
            acc[2] = fma2(ss, b1.x, acc[2]);
            acc[3] = fma2(ss, b1.y, acc[3]);
            acc[4] = fma2(ss, b2.x, acc[4]);
            acc[5] = fma2(ss, b2.y, acc[5]);
            acc[6] = fma2(ss, b3.x, acc[6]);
            acc[7] = fma2(ss, b3.y, acc[7]);

            unsigned long long t0 = mul2(cc, C1);
            unsigned long long t1 = mul2(cc, S1);
            cc = fma2(ss, nS1, t0);
            ss = fma2(ss, C1,  t1);
        }

        float* pp = &part[(rl * NJC + jc) * FN];
#pragma unroll
        for (int p = 0; p < 8; p++) {
            float lo, hi;
            upk2(acc[p], lo, hi);
            pp[2 * p + 0] = lo;
            pp[2 * p + 1] = hi;
        }
    }
    __syncthreads();

    const float q0 = sq[0];
    for (int idx = tid; idx < 32 * FN; idx += 256) {
        int rl2 = idx >> 4;
        int f   = idx & (FN - 1);
        int rr  = blockIdx.x * 32 + rl2;
        if (rr < NPAD) {
            float v = q0;
#pragma unroll
            for (int q = 0; q < NJC; q++)
                v += part[(rl2 * NJC + q) * FN + f];
            g_tab[n][rr][f] = v;
        }
    }
}

// ---------------- kernel 2: fused lamprep + eval ----------------
// grid = 148, block = 512, 1 thread/sample, explicit 10-wide load batching.
#define TAB_FLOATS (NDIMS * NPAD * RSTR)     // 54060
#define EV_WSUM   TAB_FLOATS
#define EV_SC     (EV_WSUM + 12 * FN)
#define EV_LAM2   (EV_SC + NDIMS * FN)
#define EV_FLOATS (EV_LAM2 + FN)
#define EV_SMEM_BYTES (EV_FLOATS * 4)

__global__ void __launch_bounds__(512, 1)
eval_kernel(const float* __restrict__ x,
            const float* __restrict__ lam,
            float* __restrict__ out) {
    extern __shared__ float sm[];
    float* tab   = sm;
    float* wsum  = sm + EV_WSUM;
    float* sc    = sm + EV_SC;
    float* sLam2 = sm + EV_LAM2;

    const int tid = threadIdx.x;

    // table broadcast L2 -> smem
    {
        const float4* src = (const float4*)&g_tab[0][0][0];
        float4* dst = (float4*)tab;
        for (int idx = tid; idx < TAB_FLOATS / 4; idx += 512)
            dst[idx] = src[idx];
    }
    __syncthreads();

    // --- lamprep stage 1: warps 0..11 ---
    if (tid < NDIMS * 128) {
        int n = tid >> 7;
        int i = tid & 127;
        float val[FN];
#pragma unroll
        for (int f = 0; f < FN; f++) val[f] = 0.0f;
        if (i < TCOND) {
            float t = 0.01f + 0.01f * (float)i;
            float xg = t * (float)NGRID;
            float rc = floorf(xg + 0.5f);
            float dlt = xg - rc;
            int r0 = (int)rc;
            const float* rowp = tab + n * (NPAD * RSTR) + r0 * RSTR;
            float acc[FN];
#pragma unroll
            for (int f = 0; f < FN; f++) acc[f] = 0.0f;
#pragma unroll
            for (int tt = 0; tt < WK; tt++) {
                float wgt = es_w((dlt + (float)(2 - tt)) * 0.4f);
                const float4* p4 = (const float4*)(rowp + tt * RSTR);
#pragma unroll
                for (int cq = 0; cq < 4; cq++) {
                    float4 v = p4[cq];
                    acc[4 * cq + 0] = fmaf(wgt, v.x, acc[4 * cq + 0]);
                    acc[4 * cq + 1] = fmaf(wgt, v.y, acc[4 * cq + 1]);
                    acc[4 * cq + 2] = fmaf(wgt, v.z, acc[4 * cq + 2]);
                    acc[4 * cq + 3] = fmaf(wgt, v.w, acc[4 * cq + 3]);
                }
            }
            float wt = (i == 0 || i == TCOND - 1) ? 0.005f : 0.01f;
#pragma unroll
            for (int f = 0; f < FN; f++) val[f] = wt * fmaxf(acc[f], 0.0f);
        }
#pragma unroll
        for (int off = 16; off; off >>= 1)
#pragma unroll
            for (int f = 0; f < FN; f++)
                val[f] += __shfl_down_sync(0xffffffffu, val[f], off);
        if ((tid & 31) == 0) {
            int w = tid >> 5;
#pragma unroll
            for (int f = 0; f < FN; f++)
                wsum[w * FN + f] = val[f];
        }
    }

    // --- main eval ---
    const int base = blockIdx.x * SPB;
    const bool active = (tid < SPB) && (base + tid < MTOT);
    const int m = base + (active ? tid : 0);

    const float xv0 = x[3 * m + 0];
    const float xv1 = x[3 * m + 1];
    const float xv2 = x[3 * m + 2];

    int rbase[NDIMS];
    float wts[NDIMS][WK];                 // scalar weights (reg-cheap)
#pragma unroll
    for (int n = 0; n < NDIMS; n++) {
        const float xn = (n == 0) ? xv0 : (n == 1) ? xv1 : xv2;
        float xg = xn * (float)NGRID;
        float rc = floorf(xg + 0.5f);
        float dlt = xg - rc;
        rbase[n] = (int)rc;
#pragma unroll
        for (int t = 0; t < WK; t++)
            wts[n][t] = es_w((dlt + (float)(2 - t)) * 0.4f);
    }

    unsigned long long prod[8];
#pragma unroll
    for (int n = 0; n < NDIMS; n++) {
        const float* rowbase = tab + n * (NPAD * RSTR) + rbase[n] * RSTR;

        unsigned long long hacc[2][4];
#pragma unroll
        for (int h = 0; h < 2; h++) {
            const float* rowp = rowbase + h * 8;

            // batch-load ALL 10 chunks of this (dim, half) first -> MLP = 10
            ulonglong2 La0 = ((const ulonglong2*)(rowp + 0 * RSTR))[0];
            ulonglong2 Lb0 = ((const ulonglong2*)(rowp + 0 * RSTR))[1];
            ulonglong2 La1 = ((const ulonglong2*)(rowp + 1 * RSTR))[0];
            ulonglong2 Lb1 = ((const ulonglong2*)(rowp + 1 * RSTR))[1];
            ulonglong2 La2 = ((const ulonglong2*)(rowp + 2 * RSTR))[0];
            ulonglong2 Lb2 = ((const ulonglong2*)(rowp + 2 * RSTR))[1];
            ulonglong2 La3 = ((const ulonglong2*)(rowp + 3 * RSTR))[0];
            ulonglong2 Lb3 = ((const ulonglong2*)(rowp + 3 * RSTR))[1];
            ulonglong2 La4 = ((const ulonglong2*)(rowp + 4 * RSTR))[0];
            ulonglong2 Lb4 = ((const ulonglong2*)(rowp + 4 * RSTR))[1];

            unsigned long long w0 = pk2(wts[n][0], wts[n][0]);
            unsigned long long w1 = pk2(wts[n][1], wts[n][1]);
            unsigned long long w2 = pk2(wts[n][2], wts[n][2]);
            unsigned long long w3 = pk2(wts[n][3], wts[n][3]);
            unsigned long long w4 = pk2(wts[n][4], wts[n][4]);

            unsigned long long a0, a1, a2, a3;
            a0 = mul2(w0, La0.x);  a1 = mul2(w0, La0.y);
            a2 = mul2(w0, Lb0.x);  a3 = mul2(w0, Lb0.y);
            a0 = fma2(w1, La1.x, a0);  a1 = fma2(w1, La1.y, a1);
            a2 = fma2(w1, Lb1.x, a2);  a3 = fma2(w1, Lb1.y, a3);
            a0 = fma2(w2, La2.x, a0);  a1 = fma2(w2, La2.y, a1);
            a2 = fma2(w2, Lb2.x, a2);  a3 = fma2(w2, Lb2.y, a3);
            a0 = fma2(w3, La3.x, a0);  a1 = fma2(w3, La3.y, a1);
            a2 = fma2(w3, Lb3.x, a2);  a3 = fma2(w3, Lb3.y, a3);
            a0 = fma2(w4, La4.x, a0);  a1 = fma2(w4, La4.y, a1);
            a2 = fma2(w4, Lb4.x, a2);  a3 = fma2(w4, Lb4.y, a3);

            hacc[h][0] = a0; hacc[h][1] = a1; hacc[h][2] = a2; hacc[h][3] = a3;
        }

#pragma unroll
        for (int h = 0; h < 2; h++)
#pragma unroll
            for (int q = 0; q < 4; q++) {
                float lo, hi;
                upk2(hacc[h][q], lo, hi);
                unsigned long long r = pk2(fmaxf(lo, 0.0f), fmaxf(hi, 0.0f));
                int p = h * 4 + q;
                prod[p] = (n == 0) ? r : mul2(prod[p], r);
            }
    }

    __syncthreads();   // wsum complete

    if (tid < NDIMS * FN) {
        int nn = tid >> 4;
        int f  = tid & 15;
        float s = wsum[(nn * 4 + 0) * FN + f] + wsum[(nn * 4 + 1) * FN + f]
                + wsum[(nn * 4 + 2) * FN + f] + wsum[(nn * 4 + 3) * FN + f];
        sc[tid] = 1.0f / s;
    }
    __syncthreads();
    if (tid < FN)
        sLam2[tid] = lam[tid] * sc[tid] * sc[FN + tid] * sc[2 * FN + tid];
    __syncthreads();

    float s = 0.0f;
#pragma unroll
    for (int p = 0; p < 8; p++) {
        float lo, hi;
        upk2(prod[p], lo, hi);
        // prod[p] covers f = (p<4 ? 2p,2p+1 : 8+2(p-4), 9+2(p-4))
        int f0 = (p < 4) ? (2 * p) : (8 + 2 * (p - 4));
        s = fmaf(lo, sLam2[f0], s);
        s = fmaf(hi, sLam2[f0 + 1], s);
    }
    if (active) out[m] = s;
}

// ---------------- launch ----------------
extern "C" void kernel_launch(void* const* d_in, const int* in_sizes, int n_in,
                              void* d_out, int out_size) {
    const float* x   = (const float*)d_in[0];
    const float* fr  = (const float*)d_in[1];
    const float* fi  = (const float*)d_in[2];
    const float* lam = (const float*)d_in[3];
    float* out = (float*)d_out;

    const int prep_smem = PREP_FLOATS * (int)sizeof(float);
    cudaFuncSetAttribute(prep_kernel,
                         cudaFuncAttributeMaxDynamicSharedMemorySize, prep_smem);
    prep_kernel<<<dim3((NPAD + 31) / 32, NDIMS), 256, prep_smem>>>(fr, fi);

    cudaFuncSetAttribute(eval_kernel,
                         cudaFuncAttributeMaxDynamicSharedMemorySize, EV_SMEM_BYTES);
    eval_kernel<<<NBLK, 512, EV_SMEM_BYTES>>>(x, lam, out);
}